// round 13
// baseline (speedup 1.0000x reference)
#include <cuda_runtime.h>
#include <cuda_fp16.h>
#include <cstdint>

#define D_IN   2048
#define D_OUT  2048
#define M_TOK  8192
#define RANK   16
#define NEXP   8
#define SCALING 1.0f

// fp16 operands, precomputed. Static device globals (no runtime alloc).
__device__ __half g_Xh[(size_t)M_TOK * D_IN];
__device__ __half g_Wh[(size_t)D_OUT * D_IN];
__device__ __half g_Bsh[(size_t)D_OUT * 128];   // [o][k=16e+r], masked
__device__ __half g_Ath[(size_t)D_IN * 128];    // [d][k]  (lora_A transposed)

// ---------------------------------------------------------------------------
// helpers
// ---------------------------------------------------------------------------
__device__ __forceinline__ uint32_t smem_u32(const void* p) {
    uint32_t a;
    asm("{ .reg .u64 t; cvta.to.shared.u64 t, %1; cvt.u32.u64 %0, t; }" : "=r"(a) : "l"(p));
    return a;
}
__device__ __forceinline__ void cpa16(uint32_t s, const void* g) {
    asm volatile("cp.async.cg.shared.global [%0], [%1], 16;" :: "r"(s), "l"(g));
}
__device__ __forceinline__ void cpa_commit() {
    asm volatile("cp.async.commit_group;" ::: "memory");
}
template <int N> __device__ __forceinline__ void cpa_wait() {
    asm volatile("cp.async.wait_group %0;" :: "n"(N) : "memory");
}
__device__ __forceinline__ void ldsm_x4(uint32_t addr, uint32_t& r0, uint32_t& r1,
                                        uint32_t& r2, uint32_t& r3) {
    asm volatile("ldmatrix.sync.aligned.m8n8.x4.shared.b16 {%0,%1,%2,%3}, [%4];"
                 : "=r"(r0), "=r"(r1), "=r"(r2), "=r"(r3) : "r"(addr));
}
__device__ __forceinline__ void mma_fp16(float& c0, float& c1, float& c2, float& c3,
                                         uint32_t a0, uint32_t a1, uint32_t a2, uint32_t a3,
                                         uint32_t b0, uint32_t b1) {
    asm volatile(
        "mma.sync.aligned.m16n8k16.row.col.f32.f16.f16.f32 "
        "{%0,%1,%2,%3}, {%4,%5,%6,%7}, {%8,%9}, {%0,%1,%2,%3};"
        : "+f"(c0), "+f"(c1), "+f"(c2), "+f"(c3)
        : "r"(a0), "r"(a1), "r"(a2), "r"(a3), "r"(b0), "r"(b1));
}
__device__ __forceinline__ uint2 pack_h4(float4 v) {
    __half2 p0 = __floats2half2_rn(v.x, v.y);
    __half2 p1 = __floats2half2_rn(v.z, v.w);
    uint2 u;
    u.x = *(uint32_t*)&p0;
    u.y = *(uint32_t*)&p1;
    return u;
}

// ---------------------------------------------------------------------------
// Kernel 0a: convert x -> fp16 (2 float4/thread).  [default stream]
// ---------------------------------------------------------------------------
#define NCONV ((M_TOK * D_IN / 8) / 256)   // 8192 blocks

__global__ __launch_bounds__(256) void prep_x_kernel(const float* __restrict__ x)
{
    const int t = threadIdx.x;
    size_t i4 = (size_t)blockIdx.x * 512 + t;
    float4 v0 = __ldg((const float4*)x + i4);
    float4 v1 = __ldg((const float4*)x + i4 + 256);
    *(uint2*)&g_Xh[i4 * 4] = pack_h4(v0);
    *(uint2*)&g_Xh[(i4 + 256) * 4] = pack_h4(v1);
}

// ---------------------------------------------------------------------------
// Kernel 0b: build Ath (transposed lora_A) + masked Bsh, fp16. [side stream]
//  blocks [0, NAT): Ath[d][k] = A[k][d]
//  blocks [NAT, NAT+NBS): Bsh[o][16e+r] = mask[e]*Bl[e][o][r]
// ---------------------------------------------------------------------------
#define NAT   128
#define NBS   64

__global__ __launch_bounds__(256) void prep_ab_kernel(
    const float* __restrict__ A,          // lora_A as [128, D_IN]
    const float* __restrict__ Bl,         // [E, D_OUT, R]
    const int* __restrict__ mask)
{
    const int t = threadIdx.x;
    const unsigned b = blockIdx.x;

    if (b < NAT) {
        const int d0 = (int)b * 16;
        const int k  = t >> 1;
        const int dg = (t & 1) * 8;
        float4 v0 = __ldg((const float4*)&A[(size_t)k * D_IN + d0 + dg]);
        float4 v1 = __ldg((const float4*)&A[(size_t)k * D_IN + d0 + dg + 4]);
        float vv[8] = {v0.x, v0.y, v0.z, v0.w, v1.x, v1.y, v1.z, v1.w};
#pragma unroll
        for (int j = 0; j < 8; ++j)
            g_Ath[(size_t)(d0 + dg + j) * 128 + k] = __float2half_rn(vv[j]);
        return;
    }
    {
        const int o = (int)(b - NAT) * 32 + (t >> 3);
        const int e = t & 7;
        const float sc = (__ldg(&mask[e]) != 0) ? SCALING : 0.f;
        const float* src = &Bl[(size_t)e * D_OUT * RANK + (size_t)o * RANK];
#pragma unroll
        for (int h = 0; h < 2; ++h) {
            float4 v = __ldg((const float4*)(src + h * 8));
            float4 w = __ldg((const float4*)(src + h * 8 + 4));
            v.x *= sc; v.y *= sc; v.z *= sc; v.w *= sc;
            w.x *= sc; w.y *= sc; w.z *= sc; w.w *= sc;
            uint2 a = pack_h4(v), c = pack_h4(w);
            uint32_t* dst = (uint32_t*)&g_Bsh[(size_t)o * 128 + e * 16 + h * 8];
            dst[0] = a.x; dst[1] = a.y; dst[2] = c.x; dst[3] = c.y;
        }
    }
}

// ---------------------------------------------------------------------------
// Kernel 1: fold via tensor cores (proven).
//   Weff[o,d] = W[o,d] + sum_{k<128} Bsh[o,k] * Ath[d,k]
// ---------------------------------------------------------------------------
#define FTILE_B 16384
#define FSTG_B  (2 * FTILE_B)
#define FSMEM_B (2 * FSTG_B)       // 64KB

__global__ __launch_bounds__(256, 2)
void fold_mma_kernel(const float* __restrict__ W)
{
    extern __shared__ __align__(1024) char smem[];
    const uint32_t sb = smem_u32(smem);

    const int t    = threadIdx.x;
    const int lane = t & 31;
    const int wid  = t >> 5;
    const int wm0  = (wid >> 2) * 64;
    const int wn0  = (wid & 3) * 32;
    const int d0   = blockIdx.x * 128;
    const int o0   = blockIdx.y * 128;

    const int a_row = wm0 + (lane & 7) + ((lane >> 3) & 1) * 8;
    const int a_ks  = (lane >> 4);
    const int b_row = wn0 + (lane & 7) + (lane >> 4) * 8;
    const int b_ks  = (lane >> 3) & 1;
    const int a_r7  = a_row & 7;
    const int b_r7  = b_row & 7;

    float acc[4][4][4];
#pragma unroll
    for (int i = 0; i < 4; ++i)
#pragma unroll
        for (int j = 0; j < 4; ++j)
#pragma unroll
            for (int q = 0; q < 4; ++q) acc[i][j][q] = 0.f;

#pragma unroll
    for (int s = 0; s < 2; ++s) {
        const uint32_t base = sb + s * FSTG_B;
        const int kbase = s * 64;
#pragma unroll
        for (int ii = 0; ii < 4; ++ii) {
            int c = t + ii * 256;
            int row = c >> 3, seg = c & 7;
            uint32_t soff = (uint32_t)(row * 128 + ((seg ^ (row & 7)) << 4));
            cpa16(base + soff, &g_Bsh[(size_t)(o0 + row) * 128 + kbase + seg * 8]);
            cpa16(base + FTILE_B + soff, &g_Ath[(size_t)(d0 + row) * 128 + kbase + seg * 8]);
        }
    }
    cpa_commit();
    cpa_wait<0>();
    __syncthreads();

#pragma unroll
    for (int s = 0; s < 2; ++s) {
        const uint32_t xh = sb + s * FSTG_B;
        const uint32_t wh = xh + FTILE_B;
#pragma unroll
        for (int j = 0; j < 4; ++j) {
            uint32_t ah[4][4];
            const int aks = 2 * j + a_ks;
            const uint32_t axoff = (uint32_t)((aks ^ a_r7) << 4);
#pragma unroll
            for (int mi = 0; mi < 4; ++mi) {
                const uint32_t ro = (uint32_t)((a_row + mi * 16) * 128) + axoff;
                ldsm_x4(xh + ro, ah[mi][0], ah[mi][1], ah[mi][2], ah[mi][3]);
            }
            uint32_t bh[2][4];
            const int bks = 2 * j + b_ks;
            const uint32_t bxoff = (uint32_t)((bks ^ b_r7) << 4);
#pragma unroll
            for (int ni2 = 0; ni2 < 2; ++ni2) {
                const uint32_t ro = (uint32_t)((b_row + ni2 * 16) * 128) + bxoff;
                ldsm_x4(wh + ro, bh[ni2][0], bh[ni2][1], bh[ni2][2], bh[ni2][3]);
            }
#pragma unroll
            for (int mi = 0; mi < 4; ++mi) {
#pragma unroll
                for (int ni = 0; ni < 4; ++ni) {
                    const int g = ni >> 1, o = (ni & 1) * 2;
                    float* c = acc[mi][ni];
                    mma_fp16(c[0], c[1], c[2], c[3],
                             ah[mi][0], ah[mi][1], ah[mi][2], ah[mi][3],
                             bh[g][o], bh[g][o + 1]);
                }
            }
        }
    }

    const int erow = lane >> 2;
    const int ecol = (lane & 3) * 2;
#pragma unroll
    for (int ni = 0; ni < 4; ++ni) {
        const int dcol = d0 + wn0 + ni * 8 + ecol;
#pragma unroll
        for (int mi = 0; mi < 4; ++mi) {
            const int orow = o0 + wm0 + mi * 16 + erow;
#pragma unroll
            for (int h = 0; h < 2; ++h) {
                const int r = orow + h * 8;
                float2 w = __ldg((const float2*)&W[(size_t)r * D_IN + dcol]);
                __half2 p = __floats2half2_rn(w.x + acc[mi][ni][h * 2 + 0],
                                              w.y + acc[mi][ni][h * 2 + 1]);
                *(uint32_t*)&g_Wh[(size_t)r * D_IN + dcol] = *(uint32_t*)&p;
            }
        }
    }
}

// ---------------------------------------------------------------------------
// Kernel 2: main fp16 GEMM (round-12: BM=64 BN=128, 4 warps, 3-stage,
// per-j-step fragment double buffering).
// ---------------------------------------------------------------------------
#define BK 64
#define NKT (D_IN / BK)            // 32
#define TILE_X_B 8192
#define TILE_W_B 16384
#define STG_B  (TILE_X_B + TILE_W_B)   // 24KB
#define NSTG   3
#define SMEM_B (NSTG * STG_B)      // 72KB

__global__ __launch_bounds__(128, 3)
void gemm_mma_kernel(const float* __restrict__ bias, float* __restrict__ out)
{
    extern __shared__ __align__(1024) char smem[];
    const uint32_t sb = smem_u32(smem);

    const int t    = threadIdx.x;
    const int lane = t & 31;
    const int wid  = t >> 5;
    const int wn0  = wid * 32;
    const int n0   = blockIdx.x * 128;
    const int m0   = blockIdx.y * 64;

    const int a_row = (lane & 7) + ((lane >> 3) & 1) * 8;
    const int a_ks  = (lane >> 4);
    const int b_row = wn0 + (lane & 7) + (lane >> 4) * 8;
    const int b_ks  = (lane >> 3) & 1;
    const int a_r7  = a_row & 7;
    const int b_r7  = b_row & 7;

    float acc[4][4][4];
#pragma unroll
    for (int i = 0; i < 4; ++i)
#pragma unroll
        for (int j = 0; j < 4; ++j)
#pragma unroll
            for (int q = 0; q < 4; ++q) acc[i][j][q] = 0.f;

    auto issue_stage = [&](int kt, int stg) {
        const uint32_t base = sb + stg * STG_B;
        const int kbase = kt * BK;
#pragma unroll
        for (int ii = 0; ii < 4; ++ii) {
            int c = t + ii * 128;
            int row = c >> 3, seg = c & 7;
            uint32_t soff = (uint32_t)(row * 128 + ((seg ^ (row & 7)) << 4));
            cpa16(base + soff,
                  &g_Xh[(size_t)(m0 + row) * D_IN + kbase + seg * 8]);
        }
#pragma unroll
        for (int ii = 0; ii < 8; ++ii) {
            int c = t + ii * 128;
            int row = c >> 3, seg = c & 7;
            uint32_t soff = (uint32_t)(row * 128 + ((seg ^ (row & 7)) << 4));
            cpa16(base + TILE_X_B + soff,
                  &g_Wh[(size_t)(n0 + row) * D_IN + kbase + seg * 8]);
        }
        cpa_commit();
    };

    issue_stage(0, 0);
    issue_stage(1, 1);

    uint32_t ah[2][4][4], bh[2][2][4];

    auto load_frags = [&](uint32_t xh, uint32_t wh, int j, int buf) {
        const int aks = 2 * j + a_ks;
        const uint32_t axoff = (uint32_t)((aks ^ a_r7) << 4);
#pragma unroll
        for (int mi = 0; mi < 4; ++mi) {
            const uint32_t ro = (uint32_t)((a_row + mi * 16) * 128) + axoff;
            ldsm_x4(xh + ro, ah[buf][mi][0], ah[buf][mi][1], ah[buf][mi][2], ah[buf][mi][3]);
        }
        const int bks = 2 * j + b_ks;
        const uint32_t bxoff = (uint32_t)((bks ^ b_r7) << 4);
#pragma unroll
        for (int ni2 = 0; ni2 < 2; ++ni2) {
            const uint32_t ro = (uint32_t)((b_row + ni2 * 16) * 128) + bxoff;
            ldsm_x4(wh + ro, bh[buf][ni2][0], bh[buf][ni2][1], bh[buf][ni2][2], bh[buf][ni2][3]);
        }
    };

    int stg = 0, stg2 = 2;
    for (int kt = 0; kt < NKT; ++kt) {
        if (kt == NKT - 1) cpa_wait<0>(); else cpa_wait<1>();
        __syncthreads();

        if (kt + 2 < NKT) issue_stage(kt + 2, stg2);

        const uint32_t xh = sb + stg * STG_B;
        const uint32_t wh = xh + TILE_X_B;

        load_frags(xh, wh, 0, 0);
#pragma unroll
        for (int j = 0; j < 4; ++j) {
            const int cur = j & 1;
            if (j < 3) load_frags(xh, wh, j + 1, cur ^ 1);
#pragma unroll
            for (int mi = 0; mi < 4; ++mi) {
#pragma unroll
                for (int ni = 0; ni < 4; ++ni) {
                    const int g = ni >> 1, o = (ni & 1) * 2;
                    float* c = acc[mi][ni];
                    mma_fp16(c[0], c[1], c[2], c[3],
                             ah[cur][mi][0], ah[cur][mi][1], ah[cur][mi][2], ah[cur][mi][3],
                             bh[cur][g][o], bh[cur][g][o + 1]);
                }
            }
        }

        stg  = (stg  == 2) ? 0 : stg  + 1;
        stg2 = (stg2 == 2) ? 0 : stg2 + 1;
    }

    const int erow = lane >> 2;
    const int ecol = (lane & 3) * 2;
#pragma unroll
    for (int ni = 0; ni < 4; ++ni) {
        const int ncol = n0 + wn0 + ni * 8 + ecol;
        const float b0 = __ldg(&bias[ncol]);
        const float b1 = __ldg(&bias[ncol + 1]);
#pragma unroll
        for (int mi = 0; mi < 4; ++mi) {
            const int r0 = m0 + mi * 16 + erow;
            float2 v0 = { acc[mi][ni][0] + b0, acc[mi][ni][1] + b1 };
            float2 v1 = { acc[mi][ni][2] + b0, acc[mi][ni][3] + b1 };
            *(float2*)&out[(size_t)r0 * D_OUT + ncol] = v0;
            *(float2*)&out[(size_t)(r0 + 8) * D_OUT + ncol] = v1;
        }
    }
}

// ---------------------------------------------------------------------------
// Launch: fork prep_ab->fold onto a side stream, overlapped with prep_x on
// the main (capture-origin) stream; join before the GEMM.
// Streams/events created once (not device memory; allowed).
// Inputs (metadata order): x, W, b, lora_A, lora_B, expert_mask
// ---------------------------------------------------------------------------
extern "C" void kernel_launch(void* const* d_in, const int* in_sizes, int n_in,
                              void* d_out, int out_size)
{
    const float* x    = (const float*)d_in[0];
    const float* W    = (const float*)d_in[1];
    const float* b    = (const float*)d_in[2];
    const float* lA   = (const float*)d_in[3];
    const float* lB   = (const float*)d_in[4];
    const int*   mask = (const int*)d_in[5];
    float* out = (float*)d_out;

    static cudaStream_t s2 = nullptr;
    static cudaEvent_t evFork = nullptr, evJoin = nullptr;
    static bool init_done = false;
    if (!init_done) {
        cudaFuncSetAttribute(gemm_mma_kernel,
                             cudaFuncAttributeMaxDynamicSharedMemorySize, SMEM_B);
        cudaFuncSetAttribute(fold_mma_kernel,
                             cudaFuncAttributeMaxDynamicSharedMemorySize, FSMEM_B);
        cudaStreamCreateWithFlags(&s2, cudaStreamNonBlocking);
        cudaEventCreateWithFlags(&evFork, cudaEventDisableTiming);
        cudaEventCreateWithFlags(&evJoin, cudaEventDisableTiming);
        init_done = true;
    }

    // Fork: side stream runs prep_ab -> fold, main stream runs prep_x.
    cudaEventRecord(evFork, 0);
    cudaStreamWaitEvent(s2, evFork, 0);

    prep_ab_kernel<<<NAT + NBS, 256, 0, s2>>>(lA, lB, mask);
    dim3 grid_fold(D_IN / 128, D_OUT / 128);    // (16, 16)
    fold_mma_kernel<<<grid_fold, 256, FSMEM_B, s2>>>(W);
    cudaEventRecord(evJoin, s2);

    prep_x_kernel<<<NCONV, 256>>>(x);

    // Join, then the GEMM (needs both g_Xh and g_Wh).
    cudaStreamWaitEvent(0, evJoin, 0);
    dim3 grid_gemm(D_OUT / 128, M_TOK / 64);    // (16, 128)
    gemm_mma_kernel<<<grid_gemm, 128, SMEM_B>>>(b, out);
}

// round 14
// speedup vs baseline: 1.0151x; 1.0151x over previous
#include <cuda_runtime.h>
#include <cuda_fp16.h>
#include <cstdint>

#define D_IN   2048
#define D_OUT  2048
#define M_TOK  8192
#define RANK   16
#define NEXP   8
#define SCALING 1.0f

// fp16 operands, precomputed. Static device globals (no runtime alloc).
__device__ __half g_Xh[(size_t)M_TOK * D_IN];
__device__ __half g_Wh[(size_t)D_OUT * D_IN];
__device__ __half g_Bsh[(size_t)D_OUT * 128];   // [o][k=16e+r], masked
__device__ __half g_Ath[(size_t)D_IN * 128];    // [d][k]  (lora_A transposed)

// ---------------------------------------------------------------------------
// helpers
// ---------------------------------------------------------------------------
__device__ __forceinline__ uint32_t smem_u32(const void* p) {
    uint32_t a;
    asm("{ .reg .u64 t; cvta.to.shared.u64 t, %1; cvt.u32.u64 %0, t; }" : "=r"(a) : "l"(p));
    return a;
}
__device__ __forceinline__ void cpa16(uint32_t s, const void* g) {
    asm volatile("cp.async.cg.shared.global [%0], [%1], 16;" :: "r"(s), "l"(g));
}
__device__ __forceinline__ void cpa_commit() {
    asm volatile("cp.async.commit_group;" ::: "memory");
}
template <int N> __device__ __forceinline__ void cpa_wait() {
    asm volatile("cp.async.wait_group %0;" :: "n"(N) : "memory");
}
__device__ __forceinline__ void ldsm_x4(uint32_t addr, uint32_t& r0, uint32_t& r1,
                                        uint32_t& r2, uint32_t& r3) {
    asm volatile("ldmatrix.sync.aligned.m8n8.x4.shared.b16 {%0,%1,%2,%3}, [%4];"
                 : "=r"(r0), "=r"(r1), "=r"(r2), "=r"(r3) : "r"(addr));
}
__device__ __forceinline__ void mma_fp16(float& c0, float& c1, float& c2, float& c3,
                                         uint32_t a0, uint32_t a1, uint32_t a2, uint32_t a3,
                                         uint32_t b0, uint32_t b1) {
    asm volatile(
        "mma.sync.aligned.m16n8k16.row.col.f32.f16.f16.f32 "
        "{%0,%1,%2,%3}, {%4,%5,%6,%7}, {%8,%9}, {%0,%1,%2,%3};"
        : "+f"(c0), "+f"(c1), "+f"(c2), "+f"(c3)
        : "r"(a0), "r"(a1), "r"(a2), "r"(a3), "r"(b0), "r"(b1));
}
__device__ __forceinline__ uint2 pack_h4(float4 v) {
    __half2 p0 = __floats2half2_rn(v.x, v.y);
    __half2 p1 = __floats2half2_rn(v.z, v.w);
    uint2 u;
    u.x = *(uint32_t*)&p0;
    u.y = *(uint32_t*)&p1;
    return u;
}
__device__ __forceinline__ void stcs_f2(float* p, float2 v) {
    asm volatile("st.global.cs.v2.f32 [%0], {%1, %2};" :: "l"(p), "f"(v.x), "f"(v.y) : "memory");
}

// ---------------------------------------------------------------------------
// Kernel 0 (merged prep, round-11 proven ~15.7us):
//  blocks [0, NCONV): convert x -> fp16 (2 float4/thread)
//  blocks [NCONV, NCONV+NAT): transpose lora_A -> Ath[d][k] fp16
//  blocks [NCONV+NAT, ...): build masked Bsh[o][k] fp16
// ---------------------------------------------------------------------------
#define NCONV ((M_TOK * D_IN / 8) / 256)   // 8192 blocks
#define NAT   128
#define NBS   64

__global__ __launch_bounds__(256) void prep_kernel(
    const float* __restrict__ x,
    const float* __restrict__ A,          // lora_A as [128, D_IN]
    const float* __restrict__ Bl,         // [E, D_OUT, R]
    const int* __restrict__ mask)
{
    const int t = threadIdx.x;
    const unsigned b = blockIdx.x;

    if (b < NCONV) {
        size_t i4 = (size_t)b * 512 + t;
        float4 v0 = __ldg((const float4*)x + i4);
        float4 v1 = __ldg((const float4*)x + i4 + 256);
        *(uint2*)&g_Xh[i4 * 4] = pack_h4(v0);
        *(uint2*)&g_Xh[(i4 + 256) * 4] = pack_h4(v1);
        return;
    }
    if (b < NCONV + NAT) {
        const int d0 = (int)(b - NCONV) * 16;
        const int k  = t >> 1;
        const int dg = (t & 1) * 8;
        float4 v0 = __ldg((const float4*)&A[(size_t)k * D_IN + d0 + dg]);
        float4 v1 = __ldg((const float4*)&A[(size_t)k * D_IN + d0 + dg + 4]);
        float vv[8] = {v0.x, v0.y, v0.z, v0.w, v1.x, v1.y, v1.z, v1.w};
#pragma unroll
        for (int j = 0; j < 8; ++j)
            g_Ath[(size_t)(d0 + dg + j) * 128 + k] = __float2half_rn(vv[j]);
        return;
    }
    {
        const int o = (int)(b - NCONV - NAT) * 32 + (t >> 3);
        const int e = t & 7;
        const float sc = (__ldg(&mask[e]) != 0) ? SCALING : 0.f;
        const float* src = &Bl[(size_t)e * D_OUT * RANK + (size_t)o * RANK];
#pragma unroll
        for (int h = 0; h < 2; ++h) {
            float4 v = __ldg((const float4*)(src + h * 8));
            float4 w = __ldg((const float4*)(src + h * 8 + 4));
            v.x *= sc; v.y *= sc; v.z *= sc; v.w *= sc;
            w.x *= sc; w.y *= sc; w.z *= sc; w.w *= sc;
            uint2 a = pack_h4(v), c = pack_h4(w);
            uint32_t* dst = (uint32_t*)&g_Bsh[(size_t)o * 128 + e * 16 + h * 8];
            dst[0] = a.x; dst[1] = a.y; dst[2] = c.x; dst[3] = c.y;
        }
    }
}

// ---------------------------------------------------------------------------
// Kernel 1: fold via tensor cores (proven).
//   Weff[o,d] = W[o,d] + sum_{k<128} Bsh[o,k] * Ath[d,k]
// ---------------------------------------------------------------------------
#define FTILE_B 16384
#define FSTG_B  (2 * FTILE_B)
#define FSMEM_B (2 * FSTG_B)       // 64KB

__global__ __launch_bounds__(256, 2)
void fold_mma_kernel(const float* __restrict__ W)
{
    extern __shared__ __align__(1024) char smem[];
    const uint32_t sb = smem_u32(smem);

    const int t    = threadIdx.x;
    const int lane = t & 31;
    const int wid  = t >> 5;
    const int wm0  = (wid >> 2) * 64;
    const int wn0  = (wid & 3) * 32;
    const int d0   = blockIdx.x * 128;
    const int o0   = blockIdx.y * 128;

    const int a_row = wm0 + (lane & 7) + ((lane >> 3) & 1) * 8;
    const int a_ks  = (lane >> 4);
    const int b_row = wn0 + (lane & 7) + (lane >> 4) * 8;
    const int b_ks  = (lane >> 3) & 1;
    const int a_r7  = a_row & 7;
    const int b_r7  = b_row & 7;

    float acc[4][4][4];
#pragma unroll
    for (int i = 0; i < 4; ++i)
#pragma unroll
        for (int j = 0; j < 4; ++j)
#pragma unroll
            for (int q = 0; q < 4; ++q) acc[i][j][q] = 0.f;

#pragma unroll
    for (int s = 0; s < 2; ++s) {
        const uint32_t base = sb + s * FSTG_B;
        const int kbase = s * 64;
#pragma unroll
        for (int ii = 0; ii < 4; ++ii) {
            int c = t + ii * 256;
            int row = c >> 3, seg = c & 7;
            uint32_t soff = (uint32_t)(row * 128 + ((seg ^ (row & 7)) << 4));
            cpa16(base + soff, &g_Bsh[(size_t)(o0 + row) * 128 + kbase + seg * 8]);
            cpa16(base + FTILE_B + soff, &g_Ath[(size_t)(d0 + row) * 128 + kbase + seg * 8]);
        }
    }
    cpa_commit();
    cpa_wait<0>();
    __syncthreads();

#pragma unroll
    for (int s = 0; s < 2; ++s) {
        const uint32_t xh = sb + s * FSTG_B;
        const uint32_t wh = xh + FTILE_B;
#pragma unroll
        for (int j = 0; j < 4; ++j) {
            uint32_t ah[4][4];
            const int aks = 2 * j + a_ks;
            const uint32_t axoff = (uint32_t)((aks ^ a_r7) << 4);
#pragma unroll
            for (int mi = 0; mi < 4; ++mi) {
                const uint32_t ro = (uint32_t)((a_row + mi * 16) * 128) + axoff;
                ldsm_x4(xh + ro, ah[mi][0], ah[mi][1], ah[mi][2], ah[mi][3]);
            }
            uint32_t bh[2][4];
            const int bks = 2 * j + b_ks;
            const uint32_t bxoff = (uint32_t)((bks ^ b_r7) << 4);
#pragma unroll
            for (int ni2 = 0; ni2 < 2; ++ni2) {
                const uint32_t ro = (uint32_t)((b_row + ni2 * 16) * 128) + bxoff;
                ldsm_x4(wh + ro, bh[ni2][0], bh[ni2][1], bh[ni2][2], bh[ni2][3]);
            }
#pragma unroll
            for (int mi = 0; mi < 4; ++mi) {
#pragma unroll
                for (int ni = 0; ni < 4; ++ni) {
                    const int g = ni >> 1, o = (ni & 1) * 2;
                    float* c = acc[mi][ni];
                    mma_fp16(c[0], c[1], c[2], c[3],
                             ah[mi][0], ah[mi][1], ah[mi][2], ah[mi][3],
                             bh[g][o], bh[g][o + 1]);
                }
            }
        }
    }

    const int erow = lane >> 2;
    const int ecol = (lane & 3) * 2;
#pragma unroll
    for (int ni = 0; ni < 4; ++ni) {
        const int dcol = d0 + wn0 + ni * 8 + ecol;
#pragma unroll
        for (int mi = 0; mi < 4; ++mi) {
            const int orow = o0 + wm0 + mi * 16 + erow;
#pragma unroll
            for (int h = 0; h < 2; ++h) {
                const int r = orow + h * 8;
                float2 w = __ldg((const float2*)&W[(size_t)r * D_IN + dcol]);
                __half2 p = __floats2half2_rn(w.x + acc[mi][ni][h * 2 + 0],
                                              w.y + acc[mi][ni][h * 2 + 1]);
                *(uint32_t*)&g_Wh[(size_t)r * D_IN + dcol] = *(uint32_t*)&p;
            }
        }
    }
}

// ---------------------------------------------------------------------------
// Kernel 2: main fp16 GEMM (round-12 proven geometry + streaming epilogue).
// BM=64, BN=128, 128 threads (4 warps, warp 64x32), 3-stage cp.async,
// per-j-step fragment double buffering. Epilogue uses st.global.cs so the
// 64MB one-shot output doesn't evict the X/W reuse window in L2.
// ---------------------------------------------------------------------------
#define BK 64
#define NKT (D_IN / BK)            // 32
#define TILE_X_B 8192
#define TILE_W_B 16384
#define STG_B  (TILE_X_B + TILE_W_B)   // 24KB
#define NSTG   3
#define SMEM_B (NSTG * STG_B)      // 72KB

__global__ __launch_bounds__(128, 3)
void gemm_mma_kernel(const float* __restrict__ bias, float* __restrict__ out)
{
    extern __shared__ __align__(1024) char smem[];
    const uint32_t sb = smem_u32(smem);

    const int t    = threadIdx.x;
    const int lane = t & 31;
    const int wid  = t >> 5;
    const int wn0  = wid * 32;
    const int n0   = blockIdx.x * 128;
    const int m0   = blockIdx.y * 64;

    const int a_row = (lane & 7) + ((lane >> 3) & 1) * 8;
    const int a_ks  = (lane >> 4);
    const int b_row = wn0 + (lane & 7) + (lane >> 4) * 8;
    const int b_ks  = (lane >> 3) & 1;
    const int a_r7  = a_row & 7;
    const int b_r7  = b_row & 7;

    float acc[4][4][4];
#pragma unroll
    for (int i = 0; i < 4; ++i)
#pragma unroll
        for (int j = 0; j < 4; ++j)
#pragma unroll
            for (int q = 0; q < 4; ++q) acc[i][j][q] = 0.f;

    auto issue_stage = [&](int kt, int stg) {
        const uint32_t base = sb + stg * STG_B;
        const int kbase = kt * BK;
#pragma unroll
        for (int ii = 0; ii < 4; ++ii) {
            int c = t + ii * 128;
            int row = c >> 3, seg = c & 7;
            uint32_t soff = (uint32_t)(row * 128 + ((seg ^ (row & 7)) << 4));
            cpa16(base + soff,
                  &g_Xh[(size_t)(m0 + row) * D_IN + kbase + seg * 8]);
        }
#pragma unroll
        for (int ii = 0; ii < 8; ++ii) {
            int c = t + ii * 128;
            int row = c >> 3, seg = c & 7;
            uint32_t soff = (uint32_t)(row * 128 + ((seg ^ (row & 7)) << 4));
            cpa16(base + TILE_X_B + soff,
                  &g_Wh[(size_t)(n0 + row) * D_IN + kbase + seg * 8]);
        }
        cpa_commit();
    };

    issue_stage(0, 0);
    issue_stage(1, 1);

    uint32_t ah[2][4][4], bh[2][2][4];

    auto load_frags = [&](uint32_t xh, uint32_t wh, int j, int buf) {
        const int aks = 2 * j + a_ks;
        const uint32_t axoff = (uint32_t)((aks ^ a_r7) << 4);
#pragma unroll
        for (int mi = 0; mi < 4; ++mi) {
            const uint32_t ro = (uint32_t)((a_row + mi * 16) * 128) + axoff;
            ldsm_x4(xh + ro, ah[buf][mi][0], ah[buf][mi][1], ah[buf][mi][2], ah[buf][mi][3]);
        }
        const int bks = 2 * j + b_ks;
        const uint32_t bxoff = (uint32_t)((bks ^ b_r7) << 4);
#pragma unroll
        for (int ni2 = 0; ni2 < 2; ++ni2) {
            const uint32_t ro = (uint32_t)((b_row + ni2 * 16) * 128) + bxoff;
            ldsm_x4(wh + ro, bh[buf][ni2][0], bh[buf][ni2][1], bh[buf][ni2][2], bh[buf][ni2][3]);
        }
    };

    int stg = 0, stg2 = 2;
    for (int kt = 0; kt < NKT; ++kt) {
        if (kt == NKT - 1) cpa_wait<0>(); else cpa_wait<1>();
        __syncthreads();

        if (kt + 2 < NKT) issue_stage(kt + 2, stg2);

        const uint32_t xh = sb + stg * STG_B;
        const uint32_t wh = xh + TILE_X_B;

        load_frags(xh, wh, 0, 0);
#pragma unroll
        for (int j = 0; j < 4; ++j) {
            const int cur = j & 1;
            if (j < 3) load_frags(xh, wh, j + 1, cur ^ 1);
#pragma unroll
            for (int mi = 0; mi < 4; ++mi) {
#pragma unroll
                for (int ni = 0; ni < 4; ++ni) {
                    const int g = ni >> 1, o = (ni & 1) * 2;
                    float* c = acc[mi][ni];
                    mma_fp16(c[0], c[1], c[2], c[3],
                             ah[cur][mi][0], ah[cur][mi][1], ah[cur][mi][2], ah[cur][mi][3],
                             bh[cur][g][o], bh[cur][g][o + 1]);
                }
            }
        }

        stg  = (stg  == 2) ? 0 : stg  + 1;
        stg2 = (stg2 == 2) ? 0 : stg2 + 1;
    }

    const int erow = lane >> 2;
    const int ecol = (lane & 3) * 2;
#pragma unroll
    for (int ni = 0; ni < 4; ++ni) {
        const int ncol = n0 + wn0 + ni * 8 + ecol;
        const float b0 = __ldg(&bias[ncol]);
        const float b1 = __ldg(&bias[ncol + 1]);
#pragma unroll
        for (int mi = 0; mi < 4; ++mi) {
            const int r0 = m0 + mi * 16 + erow;
            float2 v0 = { acc[mi][ni][0] + b0, acc[mi][ni][1] + b1 };
            float2 v1 = { acc[mi][ni][2] + b0, acc[mi][ni][3] + b1 };
            stcs_f2(&out[(size_t)r0 * D_OUT + ncol], v0);
            stcs_f2(&out[(size_t)(r0 + 8) * D_OUT + ncol], v1);
        }
    }
}

// ---------------------------------------------------------------------------
// Inputs (metadata order): x, W, b, lora_A, lora_B, expert_mask
// ---------------------------------------------------------------------------
extern "C" void kernel_launch(void* const* d_in, const int* in_sizes, int n_in,
                              void* d_out, int out_size)
{
    const float* x    = (const float*)d_in[0];
    const float* W    = (const float*)d_in[1];
    const float* b    = (const float*)d_in[2];
    const float* lA   = (const float*)d_in[3];
    const float* lB   = (const float*)d_in[4];
    const int*   mask = (const int*)d_in[5];
    float* out = (float*)d_out;

    static bool attr_done = false;
    if (!attr_done) {
        cudaFuncSetAttribute(gemm_mma_kernel,
                             cudaFuncAttributeMaxDynamicSharedMemorySize, SMEM_B);
        cudaFuncSetAttribute(fold_mma_kernel,
                             cudaFuncAttributeMaxDynamicSharedMemorySize, FSMEM_B);
        attr_done = true;
    }

    prep_kernel<<<NCONV + NAT + NBS, 256>>>(x, lA, lB, mask);
    dim3 grid_fold(D_IN / 128, D_OUT / 128);    // (16, 16)
    fold_mma_kernel<<<grid_fold, 256, FSMEM_B>>>(W);
    dim3 grid_gemm(D_OUT / 128, M_TOK / 64);    // (16, 128)
    gemm_mma_kernel<<<grid_gemm, 128, SMEM_B>>>(b, out);
}